// round 14
// baseline (speedup 1.0000x reference)
#include <cuda_runtime.h>
#include <math.h>

typedef unsigned long long ull;

#define BATCH   32
#define DIM     4096
#define NH      32
#define NKV     8
#define HD      128
#define MAXS    2048
#define START_T 2047
#define T_TOT   2048
#define T_HALF  1024
#define RSQRT_HD 0.088388347648318447f

// -------- device scratch --------
__device__ float g_q[BATCH * NH * HD];
__device__ float g_k[BATCH * NKV * HD];
__device__ float g_v[BATCH * NKV * HD];
// flash partials: pidx = ((b*8+kv)*2+sp)*4 + h
__device__ float g_pm[512 * 4];
__device__ float g_ps[512 * 4];
__device__ float g_po[512 * 4 * HD];

// -------- packed f32x2 helpers --------
__device__ __forceinline__ void ffma2(ull &acc, ull a, ull b) {
    asm("fma.rn.f32x2 %0, %1, %2, %0;" : "+l"(acc) : "l"(a), "l"(b));
}
__device__ __forceinline__ ull pack2(float w) {
    ull r; unsigned u = __float_as_uint(w);
    asm("mov.b64 %0, {%1, %1};" : "=l"(r) : "r"(u));
    return r;
}
__device__ __forceinline__ void red_add_v4(float *p, float a, float b, float c,
                                           float d) {
    asm volatile("red.global.add.v4.f32 [%0], {%1, %2, %3, %4};"
                 :: "l"(p), "f"(a), "f"(b), "f"(c), "f"(d) : "memory");
}

// -------- zero scratch (g_q, g_k, g_v accumulate via red.add) --------
__global__ void zero_qkv_kernel() {
    int i = blockIdx.x * 256 + threadIdx.x;        // 49152 float4 slots
    float4 z = {0.f, 0.f, 0.f, 0.f};
    if (i < 32768)       *(float4 *)&g_q[4 * i] = z;
    else if (i < 40960)  *(float4 *)&g_k[4 * (i - 32768)] = z;
    else                 *(float4 *)&g_v[4 * (i - 40960)] = z;
}
__global__ void zero_out_kernel(float *__restrict__ out) {
    int i = blockIdx.x * 256 + threadIdx.x;        // 32768 float4 slots
    float4 z = {0.f, 0.f, 0.f, 0.f};
    *(float4 *)&out[4 * i] = z;
}

// -------- GEMM inner compute: one 4-k block --------
__device__ __forceinline__ void gemm_compute4(const float4 *w,
                                              const float (*xs)[32], int k,
                                              int ty, ull (*acc)[4]) {
#pragma unroll
    for (int kk = 0; kk < 4; kk++) {
        float4 xa = *(const float4 *)&xs[k + kk][ty * 8];
        float4 xb = *(const float4 *)&xs[k + kk][ty * 8 + 4];
        ull xp[4];
        xp[0] = *(const ull *)&xa.x; xp[1] = *(const ull *)&xa.z;
        xp[2] = *(const ull *)&xb.x; xp[3] = *(const ull *)&xb.z;
        const float *wf = (const float *)&w[kk];
#pragma unroll
        for (int c = 0; c < 4; c++) {
            ull wc = pack2(wf[c]);
#pragma unroll
            for (int i = 0; i < 4; i++) ffma2(acc[c][i], xp[i], wc);
        }
    }
}

// -------- double-buffered mainloop + red.v4 epilogue over staged xs --------
__device__ __forceinline__ void gemm_main(const float *__restrict__ wp,
                                          float *__restrict__ Y, int N, int j0,
                                          int ty, const float (*xs)[32]) {
    ull acc[4][4];
#pragma unroll
    for (int c = 0; c < 4; c++)
#pragma unroll
        for (int i = 0; i < 4; i++) acc[c][i] = 0ULL;

    float4 wA[4], wB[4];
#pragma unroll
    for (int kk = 0; kk < 4; kk++)
        wA[kk] = *(const float4 *)(wp + (size_t)kk * N);

    for (int k = 0; k < 128; k += 8) {
        const float *pB = wp + (size_t)(k + 4) * N;
#pragma unroll
        for (int kk = 0; kk < 4; kk++)
            wB[kk] = *(const float4 *)(pB + (size_t)kk * N);
        gemm_compute4(wA, xs, k, ty, acc);
        if (k + 8 < 128) {
            const float *pA = wp + (size_t)(k + 8) * N;
#pragma unroll
            for (int kk = 0; kk < 4; kk++)
                wA[kk] = *(const float4 *)(pA + (size_t)kk * N);
        }
        gemm_compute4(wB, xs, k + 4, ty, acc);
    }

#pragma unroll
    for (int i = 0; i < 4; i++) {
        int bb = ty * 8 + 2 * i;
        float2 v0 = *(float2 *)&acc[0][i];
        float2 v1 = *(float2 *)&acc[1][i];
        float2 v2 = *(float2 *)&acc[2][i];
        float2 v3 = *(float2 *)&acc[3][i];
        red_add_v4(&Y[(size_t)bb * N + j0], v0.x, v1.x, v2.x, v3.x);
        red_add_v4(&Y[(size_t)(bb + 1) * N + j0], v0.y, v1.y, v2.y, v3.y);
    }
}

// -------- QKV GEMM: stage x from input, 768 CTAs --------
__device__ __forceinline__ void gemm_body(const float *__restrict__ X,
                                          const float *__restrict__ W,
                                          float *__restrict__ Y, int N,
                                          int jblock, int kbeg,
                                          float (*xs)[32]) {
    const int tid = threadIdx.x;
    for (int idx = tid; idx < 1024; idx += 256) {
        int bb = idx & 31, c = idx >> 5;
        float4 xv = *(const float4 *)(X + (size_t)bb * DIM + kbeg + 4 * c);
        xs[4 * c + 0][bb] = xv.x; xs[4 * c + 1][bb] = xv.y;
        xs[4 * c + 2][bb] = xv.z; xs[4 * c + 3][bb] = xv.w;
    }
    __syncthreads();
    const int tx = tid & 63, ty = tid >> 6;
    gemm_main(W + (size_t)kbeg * N + jblock + tx * 4, Y, N, jblock + tx * 4,
              ty, xs);
}

__global__ void __launch_bounds__(256, 3)
gemm_qkv_kernel(const float *__restrict__ X, const float *__restrict__ Wq,
                const float *__restrict__ Wk, const float *__restrict__ Wv) {
    __shared__ float xs[128][32];
    int id = blockIdx.x;
    if (id < 512) {
        gemm_body(X, Wq, g_q, 4096, (id & 15) * 256, (id >> 4) * 128, xs);
    } else {
        int id2 = id - 512;
        const float *W = (id2 & 128) ? Wv : Wk;
        float *Y = (id2 & 128) ? g_v : g_k;
        int id3 = id2 & 127;
        gemm_body(X, W, Y, 1024, (id3 & 3) * 256, (id3 >> 2) * 128, xs);
    }
}

// -------- O GEMM with fused flash-combine in staging --------
// blockIdx.y = global head hg (k-slice [hg*128, hg*128+128) of the 4096-dim).
__global__ void __launch_bounds__(256, 3)
gemm_o_kernel(const float *__restrict__ W, float *__restrict__ out) {
    __shared__ float xs[128][32];
    const int tid = threadIdx.x;
    const int hg = blockIdx.y;
    const int kvh = hg >> 2, hh = hg & 3;

    for (int idx = tid; idx < 1024; idx += 256) {
        int bb = idx & 31, c = idx >> 5;
        int p0 = ((bb * 8 + kvh) * 2 + 0) * 4 + hh;
        int p1 = p0 + 4;
        float m0 = g_pm[p0], m1 = g_pm[p1];
        float s0 = g_ps[p0], s1 = g_ps[p1];
        float M = fmaxf(m0, m1);
        float w0 = __expf(m0 - M), w1 = __expf(m1 - M);
        float inv = 1.0f / (w0 * s0 + w1 * s1);
        w0 *= inv; w1 *= inv;
        float4 o0 = *(const float4 *)&g_po[(size_t)p0 * HD + 4 * c];
        float4 o1 = *(const float4 *)&g_po[(size_t)p1 * HD + 4 * c];
        xs[4 * c + 0][bb] = w0 * o0.x + w1 * o1.x;
        xs[4 * c + 1][bb] = w0 * o0.y + w1 * o1.y;
        xs[4 * c + 2][bb] = w0 * o0.z + w1 * o1.z;
        xs[4 * c + 3][bb] = w0 * o0.w + w1 * o1.w;
    }
    __syncthreads();
    const int tx = tid & 63, ty = tid >> 6;
    const int j0 = blockIdx.x * 256 + tx * 4;
    gemm_main(W + (size_t)(hg * 128) * 4096 + j0, out, 4096, j0, ty, xs);
}

// -------- Attention, 2-way T-split: block per (b, kv, sp) --------
__global__ void __launch_bounds__(256)
attn_kernel(const float *__restrict__ kc, const float *__restrict__ vc,
            const float *__restrict__ fcos, const float *__restrict__ fsin) {
    const int b  = blockIdx.x >> 4;
    const int kv = (blockIdx.x >> 1) & 7;
    const int sp = blockIdx.x & 1;
    const int tbase = sp * T_HALF;
    const int tid = threadIdx.x;
    const int lane = tid & 31;
    const int wid = tid >> 5;
    const int hl = lane & 15;
    const int half = lane >> 4;

    __shared__ float qs[512];
    __shared__ float sc[4 * T_HALF];
    __shared__ float accs[512];
    __shared__ float red[32];
    __shared__ float gmax[4], gsum[4];

    {
        int h = tid >> 6, i = tid & 63;
        float c = fcos[i], s = fsin[i];
        const float *qb = g_q + (size_t)b * 4096 + kv * 512 + h * 128 + 2 * i;
        float xr = qb[0], xi = qb[1];
        qs[h * 128 + 2 * i]     = (xr * c - xi * s) * RSQRT_HD;
        qs[h * 128 + 2 * i + 1] = (xr * s + xi * c) * RSQRT_HD;
    }
    for (int i = tid; i < 512; i += 256) accs[i] = 0.f;
    if (sp == 1 && tid < 64) {
        int i = tid;
        float c = fcos[i], s = fsin[i];
        float *kb2 = g_k + (size_t)(b * NKV + kv) * HD + 2 * i;
        float xr = kb2[0], xi = kb2[1];
        kb2[0] = xr * c - xi * s;
        kb2[1] = xr * s + xi * c;
    }
    __syncthreads();

    ull qp[4][4];
#pragma unroll
    for (int h = 0; h < 4; h++) {
        const ull *qa = (const ull *)&qs[h * 128 + hl * 4];
        const ull *qb = (const ull *)&qs[h * 128 + hl * 4 + 64];
        qp[h][0] = qa[0]; qp[h][1] = qa[1];
        qp[h][2] = qb[0]; qp[h][3] = qb[1];
    }

    const float *kbase = kc + ((size_t)b * MAXS * NKV + kv) * HD;
    const float *knew  = g_k + (size_t)(b * NKV + kv) * HD;

    for (int tb = tbase + wid * 8; tb < tbase + T_HALF; tb += 64) {
        int t0 = tb + half, t1 = tb + 2 + half, t2 = tb + 4 + half, t3 = tb + 6 + half;
        const float *k0p = (t0 == START_T) ? knew : kbase + (size_t)t0 * (NKV * HD);
        const float *k1p = (t1 == START_T) ? knew : kbase + (size_t)t1 * (NKV * HD);
        const float *k2p = (t2 == START_T) ? knew : kbase + (size_t)t2 * (NKV * HD);
        const float *k3p = (t3 == START_T) ? knew : kbase + (size_t)t3 * (NKV * HD);
        float4 lo[4], hi[4];
        lo[0] = *(const float4 *)(k0p + hl * 4); hi[0] = *(const float4 *)(k0p + hl * 4 + 64);
        lo[1] = *(const float4 *)(k1p + hl * 4); hi[1] = *(const float4 *)(k1p + hl * 4 + 64);
        lo[2] = *(const float4 *)(k2p + hl * 4); hi[2] = *(const float4 *)(k2p + hl * 4 + 64);
        lo[3] = *(const float4 *)(k3p + hl * 4); hi[3] = *(const float4 *)(k3p + hl * 4 + 64);

        float f[4][4];
#pragma unroll
        for (int r = 0; r < 4; r++) {
            const ull *lp = (const ull *)&lo[r];
            const ull *hp = (const ull *)&hi[r];
#pragma unroll
            for (int h = 0; h < 4; h++) {
                ull s = 0ULL;
                ffma2(s, lp[0], qp[h][0]); ffma2(s, lp[1], qp[h][1]);
                ffma2(s, hp[0], qp[h][2]); ffma2(s, hp[1], qp[h][3]);
                float2 v = *(float2 *)&s;
                f[h][r] = v.x + v.y;
            }
        }
#pragma unroll
        for (int off = 8; off; off >>= 1)
#pragma unroll
            for (int h = 0; h < 4; h++) {
                f[h][0] += __shfl_xor_sync(~0u, f[h][0], off);
                f[h][1] += __shfl_xor_sync(~0u, f[h][1], off);
                f[h][2] += __shfl_xor_sync(~0u, f[h][2], off);
                f[h][3] += __shfl_xor_sync(~0u, f[h][3], off);
            }
        if (hl == 0) {
#pragma unroll
            for (int h = 0; h < 4; h++) {
                sc[h * T_HALF + t0 - tbase] = f[h][0];
                sc[h * T_HALF + t1 - tbase] = f[h][1];
                sc[h * T_HALF + t2 - tbase] = f[h][2];
                sc[h * T_HALF + t3 - tbase] = f[h][3];
            }
        }
    }
    __syncthreads();

    float m0 = -1e30f, m1 = -1e30f, m2 = -1e30f, m3 = -1e30f;
    for (int t = tid; t < T_HALF; t += 256) {
        m0 = fmaxf(m0, sc[t]);
        m1 = fmaxf(m1, sc[T_HALF + t]);
        m2 = fmaxf(m2, sc[2 * T_HALF + t]);
        m3 = fmaxf(m3, sc[3 * T_HALF + t]);
    }
#pragma unroll
    for (int off = 16; off; off >>= 1) {
        m0 = fmaxf(m0, __shfl_xor_sync(~0u, m0, off));
        m1 = fmaxf(m1, __shfl_xor_sync(~0u, m1, off));
        m2 = fmaxf(m2, __shfl_xor_sync(~0u, m2, off));
        m3 = fmaxf(m3, __shfl_xor_sync(~0u, m3, off));
    }
    if (lane == 0) { red[wid * 4 + 0] = m0; red[wid * 4 + 1] = m1;
                     red[wid * 4 + 2] = m2; red[wid * 4 + 3] = m3; }
    __syncthreads();
    if (tid < 4) {
        float m = red[tid];
#pragma unroll
        for (int w = 1; w < 8; w++) m = fmaxf(m, red[w * 4 + tid]);
        gmax[tid] = m;
    }
    __syncthreads();
    m0 = gmax[0]; m1 = gmax[1]; m2 = gmax[2]; m3 = gmax[3];

    float sm0 = 0.f, sm1 = 0.f, sm2 = 0.f, sm3 = 0.f;
    for (int t = tid; t < T_HALF; t += 256) {
        float e0 = __expf(sc[t] - m0);                sc[t] = e0;                sm0 += e0;
        float e1 = __expf(sc[T_HALF + t] - m1);       sc[T_HALF + t] = e1;       sm1 += e1;
        float e2 = __expf(sc[2 * T_HALF + t] - m2);   sc[2 * T_HALF + t] = e2;   sm2 += e2;
        float e3 = __expf(sc[3 * T_HALF + t] - m3);   sc[3 * T_HALF + t] = e3;   sm3 += e3;
    }
#pragma unroll
    for (int off = 16; off; off >>= 1) {
        sm0 += __shfl_xor_sync(~0u, sm0, off);
        sm1 += __shfl_xor_sync(~0u, sm1, off);
        sm2 += __shfl_xor_sync(~0u, sm2, off);
        sm3 += __shfl_xor_sync(~0u, sm3, off);
    }
    __syncthreads();
    if (lane == 0) { red[wid * 4 + 0] = sm0; red[wid * 4 + 1] = sm1;
                     red[wid * 4 + 2] = sm2; red[wid * 4 + 3] = sm3; }
    __syncthreads();
    if (tid < 4) {
        float s = 0.f;
#pragma unroll
        for (int w = 0; w < 8; w++) s += red[w * 4 + tid];
        gsum[tid] = s;
    }
    __syncthreads();

    ull oa[4][4];
#pragma unroll
    for (int h = 0; h < 4; h++)
#pragma unroll
        for (int j = 0; j < 4; j++) oa[h][j] = 0ULL;

    const float *vbase = vc + ((size_t)b * MAXS * NKV + kv) * HD;
    const float *vnew  = g_v + (size_t)(b * NKV + kv) * HD;
    for (int tb = tbase + wid * 8; tb < tbase + T_HALF; tb += 64) {
        int t0 = tb + half, t1 = tb + 2 + half, t2 = tb + 4 + half, t3 = tb + 6 + half;
        const float *v0p = (t0 == START_T) ? vnew : vbase + (size_t)t0 * (NKV * HD);
        const float *v1p = (t1 == START_T) ? vnew : vbase + (size_t)t1 * (NKV * HD);
        const float *v2p = (t2 == START_T) ? vnew : vbase + (size_t)t2 * (NKV * HD);
        const float *v3p = (t3 == START_T) ? vnew : vbase + (size_t)t3 * (NKV * HD);
        float4 lo[4], hi[4];
        lo[0] = *(const float4 *)(v0p + hl * 4); hi[0] = *(const float4 *)(v0p + hl * 4 + 64);
        lo[1] = *(const float4 *)(v1p + hl * 4); hi[1] = *(const float4 *)(v1p + hl * 4 + 64);
        lo[2] = *(const float4 *)(v2p + hl * 4); hi[2] = *(const float4 *)(v2p + hl * 4 + 64);
        lo[3] = *(const float4 *)(v3p + hl * 4); hi[3] = *(const float4 *)(v3p + hl * 4 + 64);
        int tt[4] = {t0 - tbase, t1 - tbase, t2 - tbase, t3 - tbase};
#pragma unroll
        for (int r = 0; r < 4; r++) {
            const ull *lp = (const ull *)&lo[r];
            const ull *hp = (const ull *)&hi[r];
#pragma unroll
            for (int h = 0; h < 4; h++) {
                ull p = pack2(sc[h * T_HALF + tt[r]]);
                ffma2(oa[h][0], lp[0], p); ffma2(oa[h][1], lp[1], p);
                ffma2(oa[h][2], hp[0], p); ffma2(oa[h][3], hp[1], p);
            }
        }
    }

#pragma unroll
    for (int h = 0; h < 4; h++)
#pragma unroll
        for (int j = 0; j < 4; j++) {
            float2 v = *(float2 *)&oa[h][j];
            v.x += __shfl_xor_sync(~0u, v.x, 16);
            v.y += __shfl_xor_sync(~0u, v.y, 16);
            if (half == 0) {
                int d = hl * 4 + (j & 1) * 2 + (j >> 1) * 64;
                atomicAdd(&accs[h * 128 + d], v.x);
                atomicAdd(&accs[h * 128 + d + 1], v.y);
            }
        }
    __syncthreads();

    const int pidx = ((b * NKV + kv) * 2 + sp) * 4;
    if (tid < 4) {
        g_pm[pidx + tid] = gmax[tid];
        g_ps[pidx + tid] = gsum[tid];
    }
    for (int i = tid; i < 512; i += 256) {
        int h = i >> 7, d = i & 127;
        g_po[(size_t)(pidx + h) * HD + d] = accs[i];
    }
}

extern "C" void kernel_launch(void *const *d_in, const int *in_sizes, int n_in,
                              void *d_out, int out_size) {
    const float *x    = (const float *)d_in[0];
    const float *wq   = (const float *)d_in[1];
    const float *wk   = (const float *)d_in[2];
    const float *wv   = (const float *)d_in[3];
    const float *wo   = (const float *)d_in[4];
    const float *kc   = (const float *)d_in[5];
    const float *vc   = (const float *)d_in[6];
    const float *fcos = (const float *)d_in[7];
    const float *fsin = (const float *)d_in[8];
    float *out = (float *)d_out;

    zero_qkv_kernel<<<192, 256>>>();                       // 0
    gemm_qkv_kernel<<<768, 256>>>(x, wq, wk, wv);          // 1
    zero_out_kernel<<<128, 256>>>(out);                    // 2
    attn_kernel<<<512, 256>>>(kc, vc, fcos, fsin);         // 3 <- ncu capture
    gemm_o_kernel<<<dim3(16, 32), 256>>>(wo, out);         // 4
}